// round 9
// baseline (speedup 1.0000x reference)
#include <cuda_runtime.h>

// Gumbel-Sinkhorn, multiplicative form (R8 chassis at 3 CTAs/SM).
//   E = exp((gamma + noise) * 5)            (once)
//   repeat niters: r_i = 1/sum_j E_ij c_j ;  c_j = 1/sum_i E_ij r_i
//   out_ij = E_ij * r_i * c_j
//
// One CTA (128 threads) per matrix, __launch_bounds__(128,3) -> 3 CTAs/SM
// (12 warps, 3 independent matrix-chains per SMSP; regs capped at 170:
// rowE 128 + ~40 working).
//  - Row pass: thread t holds row t of E in 128 registers; c read as float4
//    broadcast LDS.
//  - Col pass: warp w sweeps rows 32w..32w+31 with conflict-free LDS.128 row
//    loads; r for those rows was computed by this warp's own lanes and passes
//    through smem with only a __syncwarp().
//  - Cross-warp column reduce via part buffer (2 CTA barriers per iteration).

#define NN 128
#define STRIDE 132           // float4-aligned rows; column accesses conflict-free
#define TEMP_INV 5.0f

__global__ __launch_bounds__(128, 3) void sinkhorn_kernel(
    const float* __restrict__ gamma,
    const float* __restrict__ noise,
    const int*   __restrict__ niters_p,
    float*       __restrict__ out)
{
    extern __shared__ float smem[];
    float* Es   = smem;                    // NN * STRIDE
    float* r_s  = smem + NN * STRIDE;      // NN
    float* c_s  = r_s + NN;                // NN
    float* part = c_s + NN;                // 4 * NN  cross-warp column partials

    const int tid = threadIdx.x;
    const int w   = tid >> 5;
    const int l   = tid & 31;
    const long long base = (long long)blockIdx.x * (NN * NN);
    const int niters = *niters_p;

    // ---- Prologue: E = exp((gamma + noise) * 5), coalesced float4 ----
    const float4* g4 = reinterpret_cast<const float4*>(gamma);
    const float4* n4 = reinterpret_cast<const float4*>(noise + base);
    #pragma unroll
    for (int k = 0; k < 32; ++k) {
        int v  = k * 128 + tid;           // float4 index 0..4095
        int i  = v >> 5;                  // row
        int j4 = (v & 31) * 4;            // col
        float4 g = g4[v];
        float4 u = n4[v];
        float4 e;
        e.x = __expf((g.x + u.x) * TEMP_INV);
        e.y = __expf((g.y + u.y) * TEMP_INV);
        e.z = __expf((g.z + u.z) * TEMP_INV);
        e.w = __expf((g.w + u.w) * TEMP_INV);
        *reinterpret_cast<float4*>(&Es[i * STRIDE + j4]) = e;
    }
    c_s[tid] = 1.0f;
    __syncthreads();

    // ---- Register row cache: thread t owns row t ----
    float rowE[NN];
    #pragma unroll
    for (int m = 0; m < 32; ++m) {
        float4 e = *reinterpret_cast<const float4*>(&Es[tid * STRIDE + 4 * m]);
        rowE[4 * m + 0] = e.x;
        rowE[4 * m + 1] = e.y;
        rowE[4 * m + 2] = e.z;
        rowE[4 * m + 3] = e.w;
    }

    // ---- Sinkhorn iterations ----
    for (int it = 0; it < niters; ++it) {
        // Row pass (registers x float4-broadcast c): S_t = sum_j rowE[j]*c[j]
        float a0 = 0.f, a1 = 0.f, a2 = 0.f, a3 = 0.f;
        #pragma unroll
        for (int m = 0; m < 32; ++m) {
            float4 c = *reinterpret_cast<const float4*>(&c_s[4 * m]);
            a0 += rowE[4 * m + 0] * c.x;
            a1 += rowE[4 * m + 1] * c.y;
            a2 += rowE[4 * m + 2] * c.z;
            a3 += rowE[4 * m + 3] * c.w;
        }
        r_s[tid] = __fdividef(1.0f, (a0 + a1) + (a2 + a3));
        __syncwarp();   // warp w's col sweep only needs r_s[32w..32w+31],
                        // written by this same warp — no CTA barrier.

        // Col pass: warp w sweeps rows 32w..32w+31, LDS.128 row loads;
        // r read as 8 independent broadcast LDS.128 (pipelinable).
        float b0 = 0.f, b1 = 0.f, b2 = 0.f, b3 = 0.f;
        #pragma unroll
        for (int g = 0; g < 8; ++g) {
            float4 rv = *reinterpret_cast<const float4*>(&r_s[32 * w + 4 * g]);
            int i0 = 32 * w + 4 * g;
            float4 e0 = *reinterpret_cast<const float4*>(&Es[(i0 + 0) * STRIDE + 4 * l]);
            b0 += e0.x * rv.x; b1 += e0.y * rv.x; b2 += e0.z * rv.x; b3 += e0.w * rv.x;
            float4 e1 = *reinterpret_cast<const float4*>(&Es[(i0 + 1) * STRIDE + 4 * l]);
            b0 += e1.x * rv.y; b1 += e1.y * rv.y; b2 += e1.z * rv.y; b3 += e1.w * rv.y;
            float4 e2 = *reinterpret_cast<const float4*>(&Es[(i0 + 2) * STRIDE + 4 * l]);
            b0 += e2.x * rv.z; b1 += e2.y * rv.z; b2 += e2.z * rv.z; b3 += e2.w * rv.z;
            float4 e3 = *reinterpret_cast<const float4*>(&Es[(i0 + 3) * STRIDE + 4 * l]);
            b0 += e3.x * rv.w; b1 += e3.y * rv.w; b2 += e3.z * rv.w; b3 += e3.w * rv.w;
        }
        float4 p; p.x = b0; p.y = b1; p.z = b2; p.w = b3;
        *reinterpret_cast<float4*>(&part[w * NN + 4 * l]) = p;
        __syncthreads();

        // Cross-warp column reduce: thread t handles column t (conflict-free)
        float T = (part[0 * NN + tid] + part[1 * NN + tid])
                + (part[2 * NN + tid] + part[3 * NN + tid]);
        c_s[tid] = __fdividef(1.0f, T);
        __syncthreads();
    }

    // ---- Epilogue: out = E * r * c, coalesced float4 ----
    float4* o4 = reinterpret_cast<float4*>(out + base);
    #pragma unroll
    for (int k = 0; k < 32; ++k) {
        int v  = k * 128 + tid;
        int i  = v >> 5;
        int j4 = (v & 31) * 4;
        float ri = r_s[i];
        float4 e = *reinterpret_cast<const float4*>(&Es[i * STRIDE + j4]);
        float4 o;
        o.x = e.x * ri * c_s[j4 + 0];
        o.y = e.y * ri * c_s[j4 + 1];
        o.z = e.z * ri * c_s[j4 + 2];
        o.w = e.w * ri * c_s[j4 + 3];
        o4[v] = o;
    }
}

extern "C" void kernel_launch(void* const* d_in, const int* in_sizes, int n_in,
                              void* d_out, int out_size)
{
    // Identify inputs by element count:
    //   gamma: 128*128, noise: B*128*128 (largest), niters: 1
    int gi = -1, ni = -1, si = -1;
    long long best = -1;
    for (int k = 0; k < n_in; ++k) {
        if (in_sizes[k] == 1) { si = k; }
        else if (in_sizes[k] == NN * NN && gi < 0) { gi = k; }
        if ((long long)in_sizes[k] > best) { best = in_sizes[k]; ni = k; }
    }
    if (ni == gi) {
        for (int k = 0; k < n_in; ++k)
            if (k != gi && in_sizes[k] == NN * NN) { ni = k; break; }
    }

    const float* gamma = (const float*)d_in[gi];
    const float* noise = (const float*)d_in[ni];
    const int*   nit   = (const int*)d_in[si];
    float* out = (float*)d_out;

    int B = in_sizes[ni] / (NN * NN);

    const int smem_bytes = (NN * STRIDE + 2 * NN + 4 * NN) * (int)sizeof(float);
    static bool attr_set = false;
    if (!attr_set) {
        cudaFuncSetAttribute(sinkhorn_kernel,
                             cudaFuncAttributeMaxDynamicSharedMemorySize,
                             smem_bytes);
        attr_set = true;
    }

    sinkhorn_kernel<<<B, 128, smem_bytes>>>(gamma, noise, nit, out);
}

// round 10
// speedup vs baseline: 1.1705x; 1.1705x over previous
#include <cuda_runtime.h>

// Gumbel-Sinkhorn, multiplicative form (R8 chassis + mov-free f32x2 math).
//   E = exp((gamma + noise) * 5)            (once)
//   repeat niters: r_i = 1/sum_j E_ij c_j ;  c_j = 1/sum_i E_ij r_i
//   out_ij = E_ij * r_i * c_j
//
// One CTA (128 threads) per matrix, 2 CTAs/SM.
//  - Row pass: thread t holds row t of E in 64 packed f32x2 registers;
//    c read as ulonglong2 LDS.128 (the loaded register quad IS two aligned
//    64-bit FFMA2 operands -> no packing movs, unlike R5).
//  - Col pass: warp w sweeps rows 32w..32w+31 with conflict-free LDS.128 row
//    loads (as ulonglong2); r passes through smem with only __syncwarp().
//  - 4 packed accumulators per pass -> 16-deep FMA chains (was 32).
//  - Cross-warp column reduce via part buffer (2 CTA barriers / iteration).

#define NN 128
#define STRIDE 132           // float4-aligned rows; column accesses conflict-free
#define TEMP_INV 5.0f

typedef unsigned long long ull;

__device__ __forceinline__ void fma2(ull& d, ull a, ull b) {
    asm("fma.rn.f32x2 %0, %1, %2, %0;" : "+l"(d) : "l"(a), "l"(b));
}
__device__ __forceinline__ ull add2(ull a, ull b) {
    ull r; asm("add.rn.f32x2 %0, %1, %2;" : "=l"(r) : "l"(a), "l"(b)); return r;
}
__device__ __forceinline__ ull splat2(float x) {
    ull r; asm("mov.b64 %0, {%1, %1};" : "=l"(r) : "f"(x)); return r;
}
__device__ __forceinline__ void unpack2(ull v, float& lo, float& hi) {
    asm("mov.b64 {%0, %1}, %2;" : "=f"(lo), "=f"(hi) : "l"(v));
}

__global__ __launch_bounds__(128) void sinkhorn_kernel(
    const float* __restrict__ gamma,
    const float* __restrict__ noise,
    const int*   __restrict__ niters_p,
    float*       __restrict__ out)
{
    extern __shared__ float smem[];
    float* Es   = smem;                    // NN * STRIDE
    float* r_s  = smem + NN * STRIDE;      // NN
    float* c_s  = r_s + NN;                // NN
    float* part = c_s + NN;                // 4 * NN  cross-warp column partials

    const int tid = threadIdx.x;
    const int w   = tid >> 5;
    const int l   = tid & 31;
    const long long base = (long long)blockIdx.x * (NN * NN);
    const int niters = *niters_p;

    // ---- Prologue: E = exp((gamma + noise) * 5), coalesced float4 ----
    const float4* g4 = reinterpret_cast<const float4*>(gamma);
    const float4* n4 = reinterpret_cast<const float4*>(noise + base);
    #pragma unroll
    for (int k = 0; k < 32; ++k) {
        int v  = k * 128 + tid;           // float4 index 0..4095
        int i  = v >> 5;                  // row
        int j4 = (v & 31) * 4;            // col
        float4 g = g4[v];
        float4 u = n4[v];
        float4 e;
        e.x = __expf((g.x + u.x) * TEMP_INV);
        e.y = __expf((g.y + u.y) * TEMP_INV);
        e.z = __expf((g.z + u.z) * TEMP_INV);
        e.w = __expf((g.w + u.w) * TEMP_INV);
        *reinterpret_cast<float4*>(&Es[i * STRIDE + j4]) = e;
    }
    c_s[tid] = 1.0f;
    __syncthreads();

    // ---- Register row cache (packed pairs): thread t owns row t ----
    ull rowE[64];
    #pragma unroll
    for (int m = 0; m < 32; ++m) {
        ulonglong2 e = *reinterpret_cast<const ulonglong2*>(&Es[tid * STRIDE + 4 * m]);
        rowE[2 * m + 0] = e.x;
        rowE[2 * m + 1] = e.y;
    }

    // ---- Sinkhorn iterations ----
    for (int it = 0; it < niters; ++it) {
        // Row pass: S_t = sum_j rowE[j] * c[j]; 4 packed accumulators.
        ull a0 = 0, a1 = 0, a2 = 0, a3 = 0;
        #pragma unroll
        for (int m = 0; m < 16; ++m) {
            ulonglong2 c0 = *reinterpret_cast<const ulonglong2*>(&c_s[8 * m]);
            ulonglong2 c1 = *reinterpret_cast<const ulonglong2*>(&c_s[8 * m + 4]);
            fma2(a0, rowE[4 * m + 0], c0.x);
            fma2(a1, rowE[4 * m + 1], c0.y);
            fma2(a2, rowE[4 * m + 2], c1.x);
            fma2(a3, rowE[4 * m + 3], c1.y);
        }
        ull as = add2(add2(a0, a1), add2(a2, a3));
        float slo, shi; unpack2(as, slo, shi);
        r_s[tid] = __fdividef(1.0f, slo + shi);
        __syncwarp();   // warp w's col sweep only needs r_s[32w..32w+31],
                        // written by this same warp — no CTA barrier.

        // Col pass: warp w sweeps rows 32w..32w+31, LDS.128 row loads
        // (as ulonglong2); 4 packed accumulators (even/odd rows).
        ull b0 = 0, b1 = 0, b2 = 0, b3 = 0;
        #pragma unroll
        for (int g = 0; g < 8; ++g) {
            float4 rv = *reinterpret_cast<const float4*>(&r_s[32 * w + 4 * g]);
            ull rr0 = splat2(rv.x);
            ull rr1 = splat2(rv.y);
            ull rr2 = splat2(rv.z);
            ull rr3 = splat2(rv.w);
            int i0 = 32 * w + 4 * g;
            ulonglong2 e0 = *reinterpret_cast<const ulonglong2*>(&Es[(i0 + 0) * STRIDE + 4 * l]);
            fma2(b0, e0.x, rr0); fma2(b1, e0.y, rr0);
            ulonglong2 e1 = *reinterpret_cast<const ulonglong2*>(&Es[(i0 + 1) * STRIDE + 4 * l]);
            fma2(b2, e1.x, rr1); fma2(b3, e1.y, rr1);
            ulonglong2 e2 = *reinterpret_cast<const ulonglong2*>(&Es[(i0 + 2) * STRIDE + 4 * l]);
            fma2(b0, e2.x, rr2); fma2(b1, e2.y, rr2);
            ulonglong2 e3 = *reinterpret_cast<const ulonglong2*>(&Es[(i0 + 3) * STRIDE + 4 * l]);
            fma2(b2, e3.x, rr3); fma2(b3, e3.y, rr3);
        }
        ull p01 = add2(b0, b2);            // cols 4l, 4l+1
        ull p23 = add2(b1, b3);            // cols 4l+2, 4l+3
        ulonglong2 pv; pv.x = p01; pv.y = p23;
        *reinterpret_cast<ulonglong2*>(&part[w * NN + 4 * l]) = pv;
        __syncthreads();

        // Cross-warp column reduce: thread t handles column t (conflict-free)
        float T = (part[0 * NN + tid] + part[1 * NN + tid])
                + (part[2 * NN + tid] + part[3 * NN + tid]);
        c_s[tid] = __fdividef(1.0f, T);
        __syncthreads();
    }

    // ---- Epilogue: out = E * r * c, coalesced float4 ----
    float4* o4 = reinterpret_cast<float4*>(out + base);
    #pragma unroll
    for (int k = 0; k < 32; ++k) {
        int v  = k * 128 + tid;
        int i  = v >> 5;
        int j4 = (v & 31) * 4;
        float ri = r_s[i];
        float4 e = *reinterpret_cast<const float4*>(&Es[i * STRIDE + j4]);
        float4 o;
        o.x = e.x * ri * c_s[j4 + 0];
        o.y = e.y * ri * c_s[j4 + 1];
        o.z = e.z * ri * c_s[j4 + 2];
        o.w = e.w * ri * c_s[j4 + 3];
        o4[v] = o;
    }
}

extern "C" void kernel_launch(void* const* d_in, const int* in_sizes, int n_in,
                              void* d_out, int out_size)
{
    // Identify inputs by element count:
    //   gamma: 128*128, noise: B*128*128 (largest), niters: 1
    int gi = -1, ni = -1, si = -1;
    long long best = -1;
    for (int k = 0; k < n_in; ++k) {
        if (in_sizes[k] == 1) { si = k; }
        else if (in_sizes[k] == NN * NN && gi < 0) { gi = k; }
        if ((long long)in_sizes[k] > best) { best = in_sizes[k]; ni = k; }
    }
    if (ni == gi) {
        for (int k = 0; k < n_in; ++k)
            if (k != gi && in_sizes[k] == NN * NN) { ni = k; break; }
    }

    const float* gamma = (const float*)d_in[gi];
    const float* noise = (const float*)d_in[ni];
    const int*   nit   = (const int*)d_in[si];
    float* out = (float*)d_out;

    int B = in_sizes[ni] / (NN * NN);

    const int smem_bytes = (NN * STRIDE + 2 * NN + 4 * NN) * (int)sizeof(float);
    static bool attr_set = false;
    if (!attr_set) {
        cudaFuncSetAttribute(sinkhorn_kernel,
                             cudaFuncAttributeMaxDynamicSharedMemorySize,
                             smem_bytes);
        attr_set = true;
    }

    sinkhorn_kernel<<<B, 128, smem_bytes>>>(gamma, noise, nit, out);
}